// round 8
// baseline (speedup 1.0000x reference)
#include <cuda_runtime.h>
#include <cuda_bf16.h>
#include <cstdint>

// Quantized int8 3x3 VALID conv, hybrid tensor+fma implicit GEMM.
// Taps 0..5 (top two kernel rows) on mma.sync s8 (6x m16n8k32 per 16-px tile),
// bottom row (taps 6,7,8) + window sum on the fma pipe (dp4a).
// Exact integer math; one final fmaf.
//
// x: [64,16,256,256] int32 (int8 values), w: [16,16,3,3] int32, bias: [16] f32
// out: [64,16,254,254] f32
// out = 1e-4*( Sum x*w - 3*Wsum(x) - 7*Sum(w) + 21*144 ) + bq[co]

#define CIN 16
#define COUT 16
#define HIN 256
#define WIN 256
#define HOUT 254
#define WOUT 254
#define TH 16
#define TW 64
#define ROWS 18
#define COLS 68
#define NQUADS (4 * ROWS * 17)

__device__ unsigned g_bfrag[2][3][2][32];  // [group][mma j][reg h][lane], taps 0..5
__device__ unsigned g_w9[3][COUT][4];      // taps 6,7,8 weights, 4 cin/word
__device__ int   g_wc[COUT];               // -7*Sum(w) + 21*144
__device__ float g_bq[COUT];

__global__ void prep_kernel(const int* __restrict__ w, const float* __restrict__ bias) {
    int t = threadIdx.x;
    if (t < 384) {                   // 2 groups * 3 mma * 2 regs * 32 lanes
        int lane = t & 31;
        int rem  = t >> 5;           // 0..11
        int g = rem / 6;
        int j = (rem / 2) % 3;
        int h = rem & 1;
        int tap = 2 * j + h;
        int co = g * 8 + (lane >> 2);
        int cb = (lane & 3) << 2;
        unsigned pk = 0;
        #pragma unroll
        for (int i = 0; i < 4; i++)
            pk |= (unsigned)(w[(co * CIN + cb + i) * 9 + tap] & 0xFF) << (8 * i);
        g_bfrag[g][j][h][lane] = pk;
    }
    if (t < 192) {                   // bottom-row weights: tap 6+ti, 16 couts, 4 words
        int ti = t / 64;
        int co = (t % 64) >> 2;
        int wi = t & 3;
        unsigned pk = 0;
        #pragma unroll
        for (int i = 0; i < 4; i++)
            pk |= (unsigned)(w[(co * CIN + 4 * wi + i) * 9 + 6 + ti] & 0xFF) << (8 * i);
        g_w9[ti][co][wi] = pk;
    }
    if (t < COUT) {
        int s = 0;
        #pragma unroll 4
        for (int k = 0; k < CIN * 9; k++) s += w[t * CIN * 9 + k];
        g_wc[t] = -7 * s + 21 * CIN * 9;
        float b = bias[t];
        float r = rintf(b / 0.0001f);
        r = fminf(fmaxf(r, -2147483648.0f), 2147483647.0f);
        g_bq[t] = r * 0.0001f;
    }
}

__device__ __forceinline__ unsigned pack4(int a, int b, int c, int d) {
    unsigned t = __byte_perm((unsigned)a, (unsigned)b, 0x0040);
    unsigned u = __byte_perm((unsigned)c, (unsigned)d, 0x4000);
    return __byte_perm(t, u, 0x7610);
}
__device__ __forceinline__ void ldm4(unsigned a[4], unsigned addr) {
    asm volatile("ldmatrix.sync.aligned.m8n8.x4.shared.b16 {%0,%1,%2,%3},[%4];"
                 : "=r"(a[0]), "=r"(a[1]), "=r"(a[2]), "=r"(a[3]) : "r"(addr));
}
__device__ __forceinline__ void mma32(int c[4], const unsigned a[4], unsigned b0, unsigned b1) {
    asm volatile("mma.sync.aligned.m16n8k32.row.col.s32.s8.s8.s32 "
                 "{%0,%1,%2,%3},{%4,%5,%6,%7},{%8,%9},{%0,%1,%2,%3};"
                 : "+r"(c[0]), "+r"(c[1]), "+r"(c[2]), "+r"(c[3])
                 : "r"(a[0]), "r"(a[1]), "r"(a[2]), "r"(a[3]), "r"(b0), "r"(b1));
}
__device__ __forceinline__ int dot8(uint4 x, uint4 w, int acc) {
    int s = __dp4a((int)x.x, (int)w.x, acc);
    s = __dp4a((int)x.y, (int)w.y, s);
    s = __dp4a((int)x.z, (int)w.z, s);
    s = __dp4a((int)x.w, (int)w.w, s);
    return s;
}
__device__ __forceinline__ int sum16(uint4 x, int acc) {
    int s = __dp4a((int)x.x, 0x01010101, acc);
    s = __dp4a((int)x.y, 0x01010101, s);
    s = __dp4a((int)x.z, 0x01010101, s);
    s = __dp4a((int)x.w, 0x01010101, s);
    return s;
}

__global__ void __launch_bounds__(256, 3)
conv_kernel(const int* __restrict__ inp, float* __restrict__ out) {
    __shared__ __align__(16) unsigned sx[ROWS * COLS * 4];   // pixel-major int8 tile
    __shared__ __align__(16) uint4 sw9[3][COUT];              // bottom-row weights
    __shared__ int   swc[COUT];
    __shared__ float sbq[COUT];

    const int tid  = threadIdx.x;
    const int lane = tid & 31;
    const int wid  = tid >> 5;
    const int n    = blockIdx.z;
    const int oh0  = blockIdx.y * TH;
    const int ow0  = blockIdx.x * TW;

    const int* xin = inp + (size_t)n * CIN * HIN * WIN;

    // ---- pack input tile: int32 -> int8, planes -> pixel-contiguous ----
    for (int gi = tid; gi < NQUADS; gi += 256) {
        int g   = gi / (ROWS * 17);
        int rem = gi - g * (ROWS * 17);
        int r   = rem / 17;
        int c4  = (rem - r * 17) * 4;
        int ih = oh0 + r, iw = ow0 + c4;
        unsigned p0, p1, p2, p3;
        const int* base = xin + (size_t)(4 * g) * (HIN * WIN) + ih * WIN + iw;
        if (ih < HIN && iw + 3 < WIN) {
            int4 v0 = *(const int4*)(base);
            int4 v1 = *(const int4*)(base + HIN * WIN);
            int4 v2 = *(const int4*)(base + 2 * HIN * WIN);
            int4 v3 = *(const int4*)(base + 3 * HIN * WIN);
            p0 = pack4(v0.x, v1.x, v2.x, v3.x);
            p1 = pack4(v0.y, v1.y, v2.y, v3.y);
            p2 = pack4(v0.z, v1.z, v2.z, v3.z);
            p3 = pack4(v0.w, v1.w, v2.w, v3.w);
        } else {
            unsigned t[4];
            #pragma unroll
            for (int j = 0; j < 4; j++) {
                t[j] = 0;
                if (ih < HIN && iw + j < WIN) {
                    int v0 = base[j];
                    int v1 = base[j + HIN * WIN];
                    int v2 = base[j + 2 * HIN * WIN];
                    int v3 = base[j + 3 * HIN * WIN];
                    t[j] = pack4(v0, v1, v2, v3);
                }
            }
            p0 = t[0]; p1 = t[1]; p2 = t[2]; p3 = t[3];
        }
        unsigned* dst = &sx[(r * COLS + c4) * 4 + g];
        dst[0] = p0; dst[4] = p1; dst[8] = p2; dst[12] = p3;
    }
    if (tid < 192) ((unsigned*)sw9)[tid] = ((const unsigned*)g_w9)[tid];
    if (tid < COUT) { swc[tid] = g_wc[tid]; sbq[tid] = g_bq[tid]; }

    // ---- B fragments into registers (taps 0..5) ----
    unsigned bf[2][3][2];
    #pragma unroll
    for (int g = 0; g < 2; g++)
        #pragma unroll
        for (int j = 0; j < 3; j++) {
            bf[g][j][0] = g_bfrag[g][j][0][lane];
            bf[g][j][1] = g_bfrag[g][j][1][lane];
        }
    __syncthreads();

    const int hi = lane >> 4;
    unsigned toff[3];
    #pragma unroll
    for (int j = 0; j < 3; j++) {
        int t = 2 * j + hi;
        toff[j] = (unsigned)(((t / 3) * COLS + (t % 3)) * 16);
    }

    const int q    = lane & 3;
    const int prow = lane >> 2;
    const int co0 = 2 * q, co1 = 2 * q + 1, co2 = 8 + 2 * q, co3 = 9 + 2 * q;

    const unsigned sxa = (unsigned)__cvta_generic_to_shared(sx);
    const size_t cs = (size_t)HOUT * WOUT;
    float* obase = out + (size_t)(n * COUT) * cs;

    #pragma unroll 1
    for (int tt = wid; tt < 64; tt += 8) {
        const int r  = tt >> 2;
        const int c0 = (tt & 3) << 4;
        const unsigned tilebase = sxa + (unsigned)(((r * COLS + c0 + (lane & 15)) * 16));

        unsigned a[3][4];
        #pragma unroll
        for (int j = 0; j < 3; j++) ldm4(a[j], tilebase + toff[j]);

        int acc0[4] = {0, 0, 0, 0};
        int acc1[4] = {0, 0, 0, 0};
        #pragma unroll
        for (int j = 0; j < 3; j++) {
            mma32(acc0, a[j], bf[0][j][0], bf[0][j][1]);
            mma32(acc1, a[j], bf[1][j][0], bf[1][j][1]);
        }

        // window-sum partials from A fragments (taps 0..5)
        int s_lo = 0, s_hi = 0;
        #pragma unroll
        for (int j = 0; j < 3; j++) {
            s_lo = __dp4a((int)a[j][0], 0x01010101, s_lo);
            s_hi = __dp4a((int)a[j][1], 0x01010101, s_hi);
            s_lo = __dp4a((int)a[j][2], 0x01010101, s_lo);
            s_hi = __dp4a((int)a[j][3], 0x01010101, s_hi);
        }
        s_lo += __shfl_xor_sync(0xffffffffu, s_lo, 1);
        s_lo += __shfl_xor_sync(0xffffffffu, s_lo, 2);
        s_hi += __shfl_xor_sync(0xffffffffu, s_hi, 1);
        s_hi += __shfl_xor_sync(0xffffffffu, s_hi, 2);

        // ---- bottom row (taps 6,7,8) on fma pipe ----
        const unsigned* bp = &sx[(((r + 2) * COLS) + c0 + prow) * 4];
        int b00, b01, b02, b03, b10, b11, b12, b13;
        {
            uint4 w6a = sw9[0][co0], w7a = sw9[1][co0], w8a = sw9[2][co0];
            uint4 w6b = sw9[0][co1], w7b = sw9[1][co1], w8b = sw9[2][co1];
            uint4 w6c = sw9[0][co2], w7c = sw9[1][co2], w8c = sw9[2][co2];
            uint4 w6d = sw9[0][co3], w7d = sw9[1][co3], w8d = sw9[2][co3];
            {
                uint4 xa = *(const uint4*)bp;
                uint4 xb = *(const uint4*)(bp + 4);
                uint4 xc = *(const uint4*)(bp + 8);
                s_lo = sum16(xa, s_lo); s_lo = sum16(xb, s_lo); s_lo = sum16(xc, s_lo);
                b00 = dot8(xc, w8a, dot8(xb, w7a, dot8(xa, w6a, 0)));
                b01 = dot8(xc, w8b, dot8(xb, w7b, dot8(xa, w6b, 0)));
                b02 = dot8(xc, w8c, dot8(xb, w7c, dot8(xa, w6c, 0)));
                b03 = dot8(xc, w8d, dot8(xb, w7d, dot8(xa, w6d, 0)));
            }
            {
                uint4 xa = *(const uint4*)(bp + 32);
                uint4 xb = *(const uint4*)(bp + 36);
                uint4 xc = *(const uint4*)(bp + 40);
                s_hi = sum16(xa, s_hi); s_hi = sum16(xb, s_hi); s_hi = sum16(xc, s_hi);
                b10 = dot8(xc, w8a, dot8(xb, w7a, dot8(xa, w6a, 0)));
                b11 = dot8(xc, w8b, dot8(xb, w7b, dot8(xa, w6b, 0)));
                b12 = dot8(xc, w8c, dot8(xb, w7c, dot8(xa, w6c, 0)));
                b13 = dot8(xc, w8d, dot8(xb, w7d, dot8(xa, w6d, 0)));
            }
        }

        const int oh = oh0 + r;
        if (oh < HOUT) {
            const int wc0 = swc[co0], wc1 = swc[co1], wc2 = swc[co2], wc3 = swc[co3];
            const float bq0 = sbq[co0], bq1 = sbq[co1], bq2 = sbq[co2], bq3 = sbq[co3];
            float* ob = obase + (size_t)oh * WOUT;
            int px0 = ow0 + c0 + prow;
            int px1 = px0 + 8;
            if (px0 < WOUT) {
                ob[(size_t)co0 * cs + px0] = fmaf((float)(acc0[0] + b00 - 3 * s_lo + wc0), 1e-4f, bq0);
                ob[(size_t)co1 * cs + px0] = fmaf((float)(acc0[1] + b01 - 3 * s_lo + wc1), 1e-4f, bq1);
                ob[(size_t)co2 * cs + px0] = fmaf((float)(acc1[0] + b02 - 3 * s_lo + wc2), 1e-4f, bq2);
                ob[(size_t)co3 * cs + px0] = fmaf((float)(acc1[1] + b03 - 3 * s_lo + wc3), 1e-4f, bq3);
            }
            if (px1 < WOUT) {
                ob[(size_t)co0 * cs + px1] = fmaf((float)(acc0[2] + b10 - 3 * s_hi + wc0), 1e-4f, bq0);
                ob[(size_t)co1 * cs + px1] = fmaf((float)(acc0[3] + b11 - 3 * s_hi + wc1), 1e-4f, bq1);
                ob[(size_t)co2 * cs + px1] = fmaf((float)(acc1[2] + b12 - 3 * s_hi + wc2), 1e-4f, bq2);
                ob[(size_t)co3 * cs + px1] = fmaf((float)(acc1[3] + b13 - 3 * s_hi + wc3), 1e-4f, bq3);
            }
        }
    }
}

extern "C" void kernel_launch(void* const* d_in, const int* in_sizes, int n_in,
                              void* d_out, int out_size) {
    const int*   x    = (const int*)d_in[0];
    const int*   w    = (const int*)d_in[1];
    const float* bias = (const float*)d_in[2];
    float* outp = (float*)d_out;

    prep_kernel<<<1, 512>>>(w, bias);

    dim3 grid((WOUT + TW - 1) / TW,   // 4
              (HOUT + TH - 1) / TH,   // 16
              64);                    // batch
    conv_kernel<<<grid, 256>>>(x, outp);
}

// round 9
// speedup vs baseline: 1.0690x; 1.0690x over previous
#include <cuda_runtime.h>
#include <cuda_bf16.h>
#include <cstdint>

// Quantized int8 3x3 VALID conv, hybrid tensor+fma implicit GEMM.
// Taps 0..7 on mma.sync s8 (8x m16n8k32 per 16-px tile), tap 8 + window sum
// on the fma pipe (dp4a). 4 CTAs/SM (<=64 regs) to keep the tensor unit fed.
// Exact integer math; one final fmaf.
//
// x: [64,16,256,256] int32 (int8 values), w: [16,16,3,3] int32, bias: [16] f32
// out: [64,16,254,254] f32
// out = 1e-4*( Sum x*w - 3*Wsum(x) - 7*Sum(w) + 21*144 ) + bq[co]

#define CIN 16
#define COUT 16
#define HIN 256
#define WIN 256
#define HOUT 254
#define WOUT 254
#define TH 16
#define TW 64
#define ROWS 18
#define COLS 68
#define NQUADS (4 * ROWS * 17)

__device__ unsigned g_bfrag[2][4][2][32];  // [group][mma j][reg h][lane], taps 0..7
__device__ unsigned g_w8[COUT][4];         // tap-8 weights, 4 cin/word
__device__ int   g_wc[COUT];               // -7*Sum(w) + 21*144
__device__ float g_bq[COUT];

__global__ void prep_kernel(const int* __restrict__ w, const float* __restrict__ bias) {
    int t = threadIdx.x;
    if (t < 512) {
        int lane = t & 31;
        int rem  = t >> 5;
        int g = rem >> 3;
        int j = (rem >> 1) & 3;
        int h = rem & 1;
        int tap = 2 * j + h;
        int co = g * 8 + (lane >> 2);
        int cb = (lane & 3) << 2;
        unsigned pk = 0;
        #pragma unroll
        for (int i = 0; i < 4; i++)
            pk |= (unsigned)(w[(co * CIN + cb + i) * 9 + tap] & 0xFF) << (8 * i);
        g_bfrag[g][j][h][lane] = pk;
    }
    if (t < 64) {
        int co = t >> 2, wi = t & 3;
        unsigned pk = 0;
        #pragma unroll
        for (int i = 0; i < 4; i++)
            pk |= (unsigned)(w[(co * CIN + 4 * wi + i) * 9 + 8] & 0xFF) << (8 * i);
        g_w8[co][wi] = pk;
    }
    if (t < COUT) {
        int s = 0;
        #pragma unroll 4
        for (int k = 0; k < CIN * 9; k++) s += w[t * CIN * 9 + k];
        g_wc[t] = -7 * s + 21 * CIN * 9;
        float b = bias[t];
        float r = rintf(b / 0.0001f);
        r = fminf(fmaxf(r, -2147483648.0f), 2147483647.0f);
        g_bq[t] = r * 0.0001f;
    }
}

__device__ __forceinline__ unsigned pack4(int a, int b, int c, int d) {
    unsigned t = __byte_perm((unsigned)a, (unsigned)b, 0x0040);
    unsigned u = __byte_perm((unsigned)c, (unsigned)d, 0x4000);
    return __byte_perm(t, u, 0x7610);
}
__device__ __forceinline__ void ldm4(unsigned a[4], unsigned addr) {
    asm volatile("ldmatrix.sync.aligned.m8n8.x4.shared.b16 {%0,%1,%2,%3},[%4];"
                 : "=r"(a[0]), "=r"(a[1]), "=r"(a[2]), "=r"(a[3]) : "r"(addr));
}
__device__ __forceinline__ void mma32(int c[4], const unsigned a[4], unsigned b0, unsigned b1) {
    asm volatile("mma.sync.aligned.m16n8k32.row.col.s32.s8.s8.s32 "
                 "{%0,%1,%2,%3},{%4,%5,%6,%7},{%8,%9},{%0,%1,%2,%3};"
                 : "+r"(c[0]), "+r"(c[1]), "+r"(c[2]), "+r"(c[3])
                 : "r"(a[0]), "r"(a[1]), "r"(a[2]), "r"(a[3]), "r"(b0), "r"(b1));
}
__device__ __forceinline__ int dot8(uint4 x, uint4 w, int acc) {
    int s = __dp4a((int)x.x, (int)w.x, acc);
    s = __dp4a((int)x.y, (int)w.y, s);
    s = __dp4a((int)x.z, (int)w.z, s);
    s = __dp4a((int)x.w, (int)w.w, s);
    return s;
}
__device__ __forceinline__ int sum16(uint4 x, int acc) {
    int s = __dp4a((int)x.x, 0x01010101, acc);
    s = __dp4a((int)x.y, 0x01010101, s);
    s = __dp4a((int)x.z, 0x01010101, s);
    s = __dp4a((int)x.w, 0x01010101, s);
    return s;
}

__global__ void __launch_bounds__(256, 4)
conv_kernel(const int* __restrict__ inp, float* __restrict__ out) {
    __shared__ __align__(16) unsigned sx[ROWS * COLS * 4];   // pixel-major int8 tile
    __shared__ __align__(16) uint4 sw8[COUT];                 // tap-8 weights
    __shared__ int   swc[COUT];
    __shared__ float sbq[COUT];

    const int tid  = threadIdx.x;
    const int lane = tid & 31;
    const int wid  = tid >> 5;
    const int n    = blockIdx.z;
    const int oh0  = blockIdx.y * TH;
    const int ow0  = blockIdx.x * TW;

    const int* xin = inp + (size_t)n * CIN * HIN * WIN;

    // ---- pack input tile: int32 -> int8, planes -> pixel-contiguous ----
    for (int gi = tid; gi < NQUADS; gi += 256) {
        int g   = gi / (ROWS * 17);
        int rem = gi - g * (ROWS * 17);
        int r   = rem / 17;
        int c4  = (rem - r * 17) * 4;
        int ih = oh0 + r, iw = ow0 + c4;
        unsigned p0, p1, p2, p3;
        const int* base = xin + (size_t)(4 * g) * (HIN * WIN) + ih * WIN + iw;
        if (ih < HIN && iw + 3 < WIN) {
            int4 v0 = *(const int4*)(base);
            int4 v1 = *(const int4*)(base + HIN * WIN);
            int4 v2 = *(const int4*)(base + 2 * HIN * WIN);
            int4 v3 = *(const int4*)(base + 3 * HIN * WIN);
            p0 = pack4(v0.x, v1.x, v2.x, v3.x);
            p1 = pack4(v0.y, v1.y, v2.y, v3.y);
            p2 = pack4(v0.z, v1.z, v2.z, v3.z);
            p3 = pack4(v0.w, v1.w, v2.w, v3.w);
        } else {
            unsigned t[4];
            #pragma unroll
            for (int j = 0; j < 4; j++) {
                t[j] = 0;
                if (ih < HIN && iw + j < WIN) {
                    int v0 = base[j];
                    int v1 = base[j + HIN * WIN];
                    int v2 = base[j + 2 * HIN * WIN];
                    int v3 = base[j + 3 * HIN * WIN];
                    t[j] = pack4(v0, v1, v2, v3);
                }
            }
            p0 = t[0]; p1 = t[1]; p2 = t[2]; p3 = t[3];
        }
        unsigned* dst = &sx[(r * COLS + c4) * 4 + g];
        dst[0] = p0; dst[4] = p1; dst[8] = p2; dst[12] = p3;
    }
    if (tid < 64) ((unsigned*)sw8)[tid] = ((const unsigned*)g_w8)[tid];
    if (tid < COUT) { swc[tid] = g_wc[tid]; sbq[tid] = g_bq[tid]; }

    // ---- B fragments into registers ----
    unsigned bf[2][4][2];
    #pragma unroll
    for (int g = 0; g < 2; g++)
        #pragma unroll
        for (int j = 0; j < 4; j++) {
            bf[g][j][0] = g_bfrag[g][j][0][lane];
            bf[g][j][1] = g_bfrag[g][j][1][lane];
        }
    __syncthreads();

    const int hi = lane >> 4;
    unsigned toff[4];
    #pragma unroll
    for (int j = 0; j < 4; j++) {
        int t = 2 * j + hi;
        toff[j] = (unsigned)(((t / 3) * COLS + (t % 3)) * 16);
    }

    const int q    = lane & 3;
    const int prow = lane >> 2;
    const int co0 = 2 * q, co1 = 2 * q + 1, co2 = 8 + 2 * q, co3 = 9 + 2 * q;

    const unsigned sxa = (unsigned)__cvta_generic_to_shared(sx);
    const size_t cs = (size_t)HOUT * WOUT;
    float* obase = out + (size_t)(n * COUT) * cs;

    #pragma unroll 1
    for (int tt = wid; tt < 64; tt += 8) {
        const int r  = tt >> 2;
        const int c0 = (tt & 3) << 4;
        const unsigned tilebase = sxa + (unsigned)(((r * COLS + c0 + (lane & 15)) * 16));

        int acc0[4] = {0, 0, 0, 0};
        int acc1[4] = {0, 0, 0, 0};
        int s_lo = 0, s_hi = 0;

        // rolling 2-deep A buffer: ldm(next) overlaps mma(cur), 8 A-regs live
        unsigned acur[4], anxt[4];
        ldm4(acur, tilebase + toff[0]);
        #pragma unroll
        for (int j = 0; j < 4; j++) {
            if (j < 3) ldm4(anxt, tilebase + toff[j + 1]);
            mma32(acc0, acur, bf[0][j][0], bf[0][j][1]);
            mma32(acc1, acur, bf[1][j][0], bf[1][j][1]);
            s_lo = __dp4a((int)acur[0], 0x01010101, s_lo);
            s_hi = __dp4a((int)acur[1], 0x01010101, s_hi);
            s_lo = __dp4a((int)acur[2], 0x01010101, s_lo);
            s_hi = __dp4a((int)acur[3], 0x01010101, s_hi);
            #pragma unroll
            for (int i = 0; i < 4; i++) acur[i] = anxt[i];
        }

        // tap-8 x vectors (all 16 cin) for this lane's two pixels
        const unsigned* t8p = &sx[(((r + 2) * COLS) + c0 + prow + 2) * 4];
        uint4 xw0 = *(const uint4*)t8p;
        uint4 xw1 = *(const uint4*)(t8p + 32);

        s_lo += __shfl_xor_sync(0xffffffffu, s_lo, 1);
        s_lo += __shfl_xor_sync(0xffffffffu, s_lo, 2);
        s_hi += __shfl_xor_sync(0xffffffffu, s_hi, 1);
        s_hi += __shfl_xor_sync(0xffffffffu, s_hi, 2);
        s_lo = sum16(xw0, s_lo);
        s_hi = sum16(xw1, s_hi);

        const int oh = oh0 + r;
        if (oh < HOUT) {
            // all epilogue constants loaded here (not live across mma burst)
            uint4 w0 = sw8[co0], w1 = sw8[co1], w2 = sw8[co2], w3 = sw8[co3];
            const int wc0 = swc[co0], wc1 = swc[co1], wc2 = swc[co2], wc3 = swc[co3];
            const float bq0 = sbq[co0], bq1 = sbq[co1], bq2 = sbq[co2], bq3 = sbq[co3];
            float* ob = obase + (size_t)oh * WOUT;
            int px0 = ow0 + c0 + prow;
            int px1 = px0 + 8;
            if (px0 < WOUT) {
                ob[(size_t)co0 * cs + px0] = fmaf((float)(acc0[0] + dot8(xw0, w0, 0) - 3 * s_lo + wc0), 1e-4f, bq0);
                ob[(size_t)co1 * cs + px0] = fmaf((float)(acc0[1] + dot8(xw0, w1, 0) - 3 * s_lo + wc1), 1e-4f, bq1);
                ob[(size_t)co2 * cs + px0] = fmaf((float)(acc1[0] + dot8(xw0, w2, 0) - 3 * s_lo + wc2), 1e-4f, bq2);
                ob[(size_t)co3 * cs + px0] = fmaf((float)(acc1[1] + dot8(xw0, w3, 0) - 3 * s_lo + wc3), 1e-4f, bq3);
            }
            if (px1 < WOUT) {
                ob[(size_t)co0 * cs + px1] = fmaf((float)(acc0[2] + dot8(xw1, w0, 0) - 3 * s_hi + wc0), 1e-4f, bq0);
                ob[(size_t)co1 * cs + px1] = fmaf((float)(acc0[3] + dot8(xw1, w1, 0) - 3 * s_hi + wc1), 1e-4f, bq1);
                ob[(size_t)co2 * cs + px1] = fmaf((float)(acc1[2] + dot8(xw1, w2, 0) - 3 * s_hi + wc2), 1e-4f, bq2);
                ob[(size_t)co3 * cs + px1] = fmaf((float)(acc1[3] + dot8(xw1, w3, 0) - 3 * s_hi + wc3), 1e-4f, bq3);
            }
        }
    }
}

extern "C" void kernel_launch(void* const* d_in, const int* in_sizes, int n_in,
                              void* d_out, int out_size) {
    const int*   x    = (const int*)d_in[0];
    const int*   w    = (const int*)d_in[1];
    const float* bias = (const float*)d_in[2];
    float* outp = (float*)d_out;

    prep_kernel<<<1, 512>>>(w, bias);

    dim3 grid((WOUT + TW - 1) / TW,   // 4
              (HOUT + TH - 1) / TH,   // 16
              64);                    // batch
    conv_kernel<<<grid, 256>>>(x, outp);
}